// round 1
// baseline (speedup 1.0000x reference)
#include <cuda_runtime.h>

#define HID   128
#define NB    16
#define NPTS  10000
#define OUTD  5
#define LTOT  (NB * NPTS)      // 160000 points
#define XSTRIDE 132            // 128 + 4 pad, multiple of 4 for float4 alignment

// Scratch (device globals — no allocation allowed)
__device__ float g_gate[4 * NB * HID];   // gates per layer/batch/feature
__device__ float g_M[NB * HID * 8];      // folded Wtf@bc^T, padded to 8 floats per (b,g)
__device__ float g_c[NB * 8];            // folded btf·bc

__device__ __forceinline__ float rowdy_f(float t, float a, float w) {
    // tanh(t) + a*sin(w*t); tanh via exp (accurate ~1e-7, args bounded here)
    float e  = __expf(2.0f * t);
    float th = 1.0f - __fdividef(2.0f, e + 1.0f);
    return th + a * __sinf(w * t);
}

// ---------------------------------------------------------------------------
// Kernel 1: branch MLP, gates, and folded final matrices. grid=16 (one block
// per batch), block=128 (one thread per feature). Tiny (~2 us).
// ---------------------------------------------------------------------------
__global__ void branch_kernel(
    const float* __restrict__ params, const float* __restrict__ Wb0,
    const float* __restrict__ bb0,    const float* __restrict__ Wb,
    const float* __restrict__ bb,     const float* __restrict__ Wbf,
    const float* __restrict__ bbf,    const float* __restrict__ ab,
    const float* __restrict__ wb,     const float* __restrict__ Wtf,
    const float* __restrict__ btf)
{
    const int b = blockIdx.x;
    const int j = threadIdx.x;

    __shared__ float sh_h[HID];
    __shared__ float sh_bc[OUTD][HID];
    __shared__ float sh_p[8];

    if (j < 6) sh_p[j] = params[b * 6 + j];
    __syncthreads();

    // layer 0 (6 -> 128)
    float t = bb0[j];
#pragma unroll
    for (int k = 0; k < 6; k++) t += sh_p[k] * Wb0[k * HID + j];
    float h    = rowdy_f(t, ab[j], wb[j]);
    float gate = h;
    sh_h[j] = h;
    g_gate[(0 * NB + b) * HID + j] = gate;
    __syncthreads();

    // layers 1..3 (128 -> 128)
    for (int i = 0; i < 3; i++) {
        const float* W = Wb + i * HID * HID;
        float t2 = bb[i * HID + j];
#pragma unroll 8
        for (int k = 0; k < HID; k++) t2 += sh_h[k] * W[k * HID + j];
        __syncthreads();            // all reads of sh_h done
        h = rowdy_f(t2, ab[(i + 1) * HID + j], wb[(i + 1) * HID + j]);
        sh_h[j] = h;
        gate += h;
        g_gate[((i + 1) * NB + b) * HID + j] = gate;
        __syncthreads();            // new sh_h visible
    }

    // branch_out -> bc[o][j] = branch_out[b][o*HID + j]
#pragma unroll
    for (int o = 0; o < OUTD; o++) {
        float s = bbf[o * HID + j];
#pragma unroll 8
        for (int k = 0; k < HID; k++)
            s += sh_h[k] * Wbf[k * (HID * OUTD) + o * HID + j];
        sh_bc[o][j] = s;
    }
    __syncthreads();

    // Fold final linear + contraction:
    //   M[b][g][o] = sum_h Wtf[g][h] * bc[o][h]
    //   c[b][o]    = sum_h btf[h]    * bc[o][h]
    {
        float accm[OUTD] = {0.f, 0.f, 0.f, 0.f, 0.f};
#pragma unroll 4
        for (int hh = 0; hh < HID; hh++) {
            float w = __ldg(&Wtf[j * HID + hh]);
#pragma unroll
            for (int o = 0; o < OUTD; o++) accm[o] += w * sh_bc[o][hh];
        }
#pragma unroll
        for (int o = 0; o < OUTD; o++) g_M[(b * HID + j) * 8 + o] = accm[o];
        for (int o = OUTD; o < 8; o++) g_M[(b * HID + j) * 8 + o] = 0.f;
    }
    if (j < OUTD) {
        float c = 0.f;
#pragma unroll 8
        for (int hh = 0; hh < HID; hh++) c += btf[hh] * sh_bc[j][hh];
        g_c[b * 8 + j] = c;
    }
    if (j >= OUTD && j < 8) g_c[b * 8 + j] = 0.f;
}

// ---------------------------------------------------------------------------
// Kernel 2: fused trunk. Each block = 128 points, 256 threads, 8x8 register
// tiles, activations transposed in SMEM (Xs[k][p]), weights staged in SMEM.
// ---------------------------------------------------------------------------
extern "C" __global__ void __launch_bounds__(256, 1)
trunk_kernel(const float* __restrict__ coords, const float* __restrict__ sdf,
             const float* __restrict__ Wt0,    const float* __restrict__ bt0,
             const float* __restrict__ Wt,     const float* __restrict__ bt,
             const float* __restrict__ at,     const float* __restrict__ wt,
             float* __restrict__ out)
{
    extern __shared__ float smem[];
    float* Xs = smem;                       // [128][XSTRIDE]
    float* Ws = smem + HID * XSTRIDE;       // [128][XSTRIDE]

    const int tid = threadIdx.x;
    const int tx  = tid & 15;               // feature group
    const int ty  = tid >> 4;               // point group
    const int p0  = blockIdx.x * 128;

    int prow[8], jcol[8], bidx[8];
#pragma unroll
    for (int i = 0; i < 4; i++) {
        prow[i]     = ty * 4 + i;
        prow[i + 4] = 64 + ty * 4 + i;
        jcol[i]     = tx * 4 + i;
        jcol[i + 4] = 64 + tx * 4 + i;
    }
#pragma unroll
    for (int i = 0; i < 8; i++) bidx[i] = (p0 + prow[i]) / NPTS;

    float acc[8][8];

    // ---- layer 0: (coords,sdf) 4 -> 128 ----
    {
        float in4[8][4];
#pragma unroll
        for (int pp = 0; pp < 8; pp++) {
            int gp = p0 + prow[pp];
            in4[pp][0] = coords[gp * 3 + 0];
            in4[pp][1] = coords[gp * 3 + 1];
            in4[pp][2] = coords[gp * 3 + 2];
            in4[pp][3] = sdf[gp];
        }
        float w0[8][4];
#pragma unroll
        for (int jj = 0; jj < 8; jj++)
#pragma unroll
            for (int k = 0; k < 4; k++)
                w0[jj][k] = __ldg(&Wt0[k * HID + jcol[jj]]);
#pragma unroll
        for (int pp = 0; pp < 8; pp++)
#pragma unroll
            for (int jj = 0; jj < 8; jj++) {
                float s = in4[pp][0] * w0[jj][0];
                s += in4[pp][1] * w0[jj][1];
                s += in4[pp][2] * w0[jj][2];
                s += in4[pp][3] * w0[jj][3];
                acc[pp][jj] = s;
            }
        // epilogue l=0
        float btv[8], av[8], wv[8];
#pragma unroll
        for (int jj = 0; jj < 8; jj++) {
            int j = jcol[jj];
            btv[jj] = __ldg(&bt0[j]);
            av[jj]  = __ldg(&at[0 * HID + j]);
            wv[jj]  = __ldg(&wt[0 * HID + j]);
        }
#pragma unroll
        for (int pp = 0; pp < 8; pp++) {
            const float* grow = &g_gate[(0 * NB + bidx[pp]) * HID];
#pragma unroll
            for (int jj = 0; jj < 8; jj++) {
                float tpre = acc[pp][jj] + btv[jj];
                float val  = rowdy_f(tpre, av[jj], wv[jj]) * __ldg(&grow[jcol[jj]]);
                Xs[jcol[jj] * XSTRIDE + prow[pp]] = val;
            }
        }
    }
    __syncthreads();

    // ---- layers 1..3: 128 -> 128 GEMM + rowdy + gate ----
    for (int l = 1; l < 4; l++) {
        // stage weights W_l (k-major [k][j]) into SMEM, coalesced float4
        const float4* Wg = (const float4*)(Wt + (l - 1) * HID * HID);
#pragma unroll
        for (int i = 0; i < 16; i++) {
            int idx = tid + i * 256;            // float4 index, 0..4095
            float4 v = __ldg(&Wg[idx]);
            int r = idx >> 5;                   // row k
            int c = (idx & 31) * 4;             // col j
            *(float4*)&Ws[r * XSTRIDE + c] = v;
        }
        __syncthreads();

#pragma unroll
        for (int pp = 0; pp < 8; pp++)
#pragma unroll
            for (int jj = 0; jj < 8; jj++) acc[pp][jj] = 0.f;

#pragma unroll 2
        for (int k = 0; k < HID; k++) {
            float4 a0 = *(const float4*)&Xs[k * XSTRIDE + ty * 4];
            float4 a1 = *(const float4*)&Xs[k * XSTRIDE + 64 + ty * 4];
            float4 b0 = *(const float4*)&Ws[k * XSTRIDE + tx * 4];
            float4 b1 = *(const float4*)&Ws[k * XSTRIDE + 64 + tx * 4];
            float av8[8] = {a0.x, a0.y, a0.z, a0.w, a1.x, a1.y, a1.z, a1.w};
            float bv8[8] = {b0.x, b0.y, b0.z, b0.w, b1.x, b1.y, b1.z, b1.w};
#pragma unroll
            for (int pp = 0; pp < 8; pp++)
#pragma unroll
                for (int jj = 0; jj < 8; jj++)
                    acc[pp][jj] += av8[pp] * bv8[jj];
        }
        __syncthreads();    // all Xs/Ws reads done

        // epilogue: rowdy + gate, write back transposed
        const float* bvec = bt + (l - 1) * HID;
        float btv[8], av[8], wv[8];
#pragma unroll
        for (int jj = 0; jj < 8; jj++) {
            int j = jcol[jj];
            btv[jj] = __ldg(&bvec[j]);
            av[jj]  = __ldg(&at[l * HID + j]);
            wv[jj]  = __ldg(&wt[l * HID + j]);
        }
#pragma unroll
        for (int pp = 0; pp < 8; pp++) {
            const float* grow = &g_gate[(l * NB + bidx[pp]) * HID];
#pragma unroll
            for (int jj = 0; jj < 8; jj++) {
                float tpre = acc[pp][jj] + btv[jj];
                float val  = rowdy_f(tpre, av[jj], wv[jj]) * __ldg(&grow[jcol[jj]]);
                Xs[jcol[jj] * XSTRIDE + prow[pp]] = val;
            }
        }
        __syncthreads();
    }

    // ---- folded final: out[p][o] = c[b][o] + sum_g Xs[g][p] * M[b][g][o] ----
    if (tid < 128) {
        const int p  = tid;
        const int gp = p0 + p;
        const int b  = gp / NPTS;
        float o0 = g_c[b * 8 + 0], o1 = g_c[b * 8 + 1], o2 = g_c[b * 8 + 2];
        float o3 = g_c[b * 8 + 3], o4 = g_c[b * 8 + 4];
        const float4* Mb = (const float4*)&g_M[b * HID * 8];
#pragma unroll 4
        for (int g = 0; g < HID; g++) {
            float v   = Xs[g * XSTRIDE + p];
            float4 m0 = __ldg(&Mb[g * 2 + 0]);
            float4 m1 = __ldg(&Mb[g * 2 + 1]);
            o0 += v * m0.x; o1 += v * m0.y; o2 += v * m0.z; o3 += v * m0.w;
            o4 += v * m1.x;
        }
        float* op = out + (size_t)gp * OUTD;
        op[0] = o0; op[1] = o1; op[2] = o2; op[3] = o3; op[4] = o4;
    }
}

// ---------------------------------------------------------------------------
extern "C" void kernel_launch(void* const* d_in, const int* in_sizes, int n_in,
                              void* d_out, int out_size)
{
    // metadata order:
    // 0 coords, 1 sdf, 2 params, 3 Wb0, 4 bb0, 5 Wb, 6 bb, 7 Wbf, 8 bbf,
    // 9 ab, 10 wb, 11 Wt0, 12 bt0, 13 Wt, 14 bt, 15 Wtf, 16 btf, 17 at, 18 wt
    const float* coords = (const float*)d_in[0];
    const float* sdf    = (const float*)d_in[1];
    const float* params = (const float*)d_in[2];
    const float* Wb0    = (const float*)d_in[3];
    const float* bb0    = (const float*)d_in[4];
    const float* Wb     = (const float*)d_in[5];
    const float* bb     = (const float*)d_in[6];
    const float* Wbf    = (const float*)d_in[7];
    const float* bbf    = (const float*)d_in[8];
    const float* ab     = (const float*)d_in[9];
    const float* wb     = (const float*)d_in[10];
    const float* Wt0    = (const float*)d_in[11];
    const float* bt0    = (const float*)d_in[12];
    const float* Wt     = (const float*)d_in[13];
    const float* bt     = (const float*)d_in[14];
    const float* Wtf    = (const float*)d_in[15];
    const float* btf    = (const float*)d_in[16];
    const float* at     = (const float*)d_in[17];
    const float* wt     = (const float*)d_in[18];
    float* out = (float*)d_out;

    static int smem_set = 0;
    const int smem_bytes = 2 * HID * XSTRIDE * sizeof(float);   // 135168
    if (!smem_set) {
        cudaFuncSetAttribute(trunk_kernel,
                             cudaFuncAttributeMaxDynamicSharedMemorySize,
                             smem_bytes);
        smem_set = 1;
    }

    branch_kernel<<<NB, HID>>>(params, Wb0, bb0, Wb, bb, Wbf, bbf, ab, wb,
                               Wtf, btf);
    trunk_kernel<<<LTOT / 128, 256, smem_bytes>>>(coords, sdf, Wt0, bt0,
                                                  Wt, bt, at, wt, out);
}

// round 2
// speedup vs baseline: 1.1959x; 1.1959x over previous
#include <cuda_runtime.h>

#define HID   128
#define NB    16
#define NPTS  10000
#define OUTD  5
#define LTOT  (NB * NPTS)      // 160000 points
#define XSTRIDE 132            // 128 + 4 pad, multiple of 4 for float4 alignment

// Scratch (device globals — no allocation allowed)
__device__ float g_gate[4 * NB * HID];   // gates per layer/batch/feature
__device__ float g_M[NB * HID * 8];      // folded Wtf@bc^T, padded to 8 floats per (b,g)
__device__ float g_c[NB * 8];            // folded btf·bc

typedef unsigned long long u64;

__device__ __forceinline__ u64 pack2(float lo, float hi) {
    u64 r; asm("mov.b64 %0, {%1, %2};" : "=l"(r) : "f"(lo), "f"(hi)); return r;
}
__device__ __forceinline__ void unpack2(u64 v, float& lo, float& hi) {
    asm("mov.b64 {%0, %1}, %2;" : "=f"(lo), "=f"(hi) : "l"(v));
}
__device__ __forceinline__ void ffma2(u64& d, u64 a, u64 b) {
    asm("fma.rn.f32x2 %0, %1, %2, %0;" : "+l"(d) : "l"(a), "l"(b));
}

__device__ __forceinline__ float rowdy_f(float t, float a, float w) {
    float th; asm("tanh.approx.f32 %0, %1;" : "=f"(th) : "f"(t));
    return th + a * __sinf(w * t);
}

// ---------------------------------------------------------------------------
// Kernel 1: branch MLP, gates, and folded final matrices. grid=16, block=128.
// ---------------------------------------------------------------------------
__global__ void branch_kernel(
    const float* __restrict__ params, const float* __restrict__ Wb0,
    const float* __restrict__ bb0,    const float* __restrict__ Wb,
    const float* __restrict__ bb,     const float* __restrict__ Wbf,
    const float* __restrict__ bbf,    const float* __restrict__ ab,
    const float* __restrict__ wb,     const float* __restrict__ Wtf,
    const float* __restrict__ btf)
{
    const int b = blockIdx.x;
    const int j = threadIdx.x;

    __shared__ float sh_h[HID];
    __shared__ float sh_bc[OUTD][HID];
    __shared__ float sh_p[8];

    if (j < 6) sh_p[j] = params[b * 6 + j];
    __syncthreads();

    // layer 0 (6 -> 128)
    float t = bb0[j];
#pragma unroll
    for (int k = 0; k < 6; k++) t += sh_p[k] * Wb0[k * HID + j];
    float h    = rowdy_f(t, ab[j], wb[j]);
    float gate = h;
    sh_h[j] = h;
    g_gate[(0 * NB + b) * HID + j] = gate;
    __syncthreads();

    // layers 1..3 (128 -> 128)
    for (int i = 0; i < 3; i++) {
        const float* W = Wb + i * HID * HID;
        float t2 = bb[i * HID + j];
#pragma unroll 8
        for (int k = 0; k < HID; k++) t2 += sh_h[k] * W[k * HID + j];
        __syncthreads();
        h = rowdy_f(t2, ab[(i + 1) * HID + j], wb[(i + 1) * HID + j]);
        sh_h[j] = h;
        gate += h;
        g_gate[((i + 1) * NB + b) * HID + j] = gate;
        __syncthreads();
    }

    // branch_out -> bc[o][j]
#pragma unroll
    for (int o = 0; o < OUTD; o++) {
        float s = bbf[o * HID + j];
#pragma unroll 8
        for (int k = 0; k < HID; k++)
            s += sh_h[k] * Wbf[k * (HID * OUTD) + o * HID + j];
        sh_bc[o][j] = s;
    }
    __syncthreads();

    // Fold final linear + contraction
    {
        float accm[OUTD] = {0.f, 0.f, 0.f, 0.f, 0.f};
#pragma unroll 4
        for (int hh = 0; hh < HID; hh++) {
            float w = __ldg(&Wtf[j * HID + hh]);
#pragma unroll
            for (int o = 0; o < OUTD; o++) accm[o] += w * sh_bc[o][hh];
        }
#pragma unroll
        for (int o = 0; o < OUTD; o++) g_M[(b * HID + j) * 8 + o] = accm[o];
        for (int o = OUTD; o < 8; o++) g_M[(b * HID + j) * 8 + o] = 0.f;
    }
    if (j < OUTD) {
        float c = 0.f;
#pragma unroll 8
        for (int hh = 0; hh < HID; hh++) c += btf[hh] * sh_bc[j][hh];
        g_c[b * 8 + j] = c;
    }
    if (j >= OUTD && j < 8) g_c[b * 8 + j] = 0.f;
}

// ---------------------------------------------------------------------------
// Kernel 2: fused trunk. Block = 128 points x 128 features, 512 threads,
// 4x8 register tile per thread, packed f32x2 FMAs, weight double-buffer
// through registers.
// ---------------------------------------------------------------------------
extern "C" __global__ void __launch_bounds__(512, 1)
trunk_kernel(const float* __restrict__ coords, const float* __restrict__ sdf,
             const float* __restrict__ Wt0,    const float* __restrict__ bt0,
             const float* __restrict__ Wt,     const float* __restrict__ bt,
             const float* __restrict__ at,     const float* __restrict__ wt,
             float* __restrict__ out)
{
    extern __shared__ float smem[];
    float* Xs = smem;                       // [128][XSTRIDE] activations (k-major, transposed)
    float* Ws = smem + HID * XSTRIDE;       // [128][XSTRIDE] weights

    const int tid   = threadIdx.x;
    const int tx    = tid & 15;             // feature group
    const int ty    = tid >> 4;             // point group 0..31
    const int p0    = blockIdx.x * 128;
    const int j0    = tx * 4;               // features j0..j0+3 and 64+j0..64+j0+3
    const int pbase = ty * 4;

    int jcol[8];
#pragma unroll
    for (int i = 0; i < 4; i++) { jcol[i] = j0 + i; jcol[i + 4] = 64 + j0 + i; }
    int bidx[4];
#pragma unroll
    for (int i = 0; i < 4; i++) bidx[i] = (p0 + pbase + i) / NPTS;

    // prefetch layer-1 weights into registers (64 KB / block, 8 float4/thread)
    float4 wreg[8];
#pragma unroll
    for (int i = 0; i < 8; i++)
        wreg[i] = __ldg(&((const float4*)Wt)[tid + i * 512]);

    // ---- layer 0: (coords,sdf) 4 -> 128 ----
    {
        float in4[4][4];
#pragma unroll
        for (int pp = 0; pp < 4; pp++) {
            int gp = p0 + pbase + pp;
            in4[pp][0] = coords[gp * 3 + 0];
            in4[pp][1] = coords[gp * 3 + 1];
            in4[pp][2] = coords[gp * 3 + 2];
            in4[pp][3] = sdf[gp];
        }
        float w0[8][4];
#pragma unroll
        for (int jj = 0; jj < 8; jj++)
#pragma unroll
            for (int k = 0; k < 4; k++)
                w0[jj][k] = __ldg(&Wt0[k * HID + jcol[jj]]);

        float val[4][8];
#pragma unroll
        for (int jj = 0; jj < 8; jj++) {
            int j = jcol[jj];
            float btv = __ldg(&bt0[j]);
            float av  = __ldg(&at[j]);
            float wv  = __ldg(&wt[j]);
#pragma unroll
            for (int pp = 0; pp < 4; pp++) {
                float s = btv;
                s += in4[pp][0] * w0[jj][0];
                s += in4[pp][1] * w0[jj][1];
                s += in4[pp][2] * w0[jj][2];
                s += in4[pp][3] * w0[jj][3];
                float g = __ldg(&g_gate[(0 * NB + bidx[pp]) * HID + j]);
                val[pp][jj] = rowdy_f(s, av, wv) * g;
            }
        }
#pragma unroll
        for (int jj = 0; jj < 8; jj++) {
            float4 v = make_float4(val[0][jj], val[1][jj], val[2][jj], val[3][jj]);
            *(float4*)&Xs[jcol[jj] * XSTRIDE + pbase] = v;
        }
    }
    __syncthreads();

    // ---- layers 1..3 ----
    for (int l = 1; l < 4; l++) {
        // stage prefetched weights into SMEM (prev k-loop reads done: covered
        // by the barrier we just passed)
#pragma unroll
        for (int i = 0; i < 8; i++) {
            int idx = tid + i * 512;          // float4 index 0..4095
            int r = idx >> 5;                 // row k
            int c = (idx & 31) * 4;           // col j
            *(float4*)&Ws[r * XSTRIDE + c] = wreg[i];
        }
        if (l < 3) {
#pragma unroll
            for (int i = 0; i < 8; i++)
                wreg[i] = __ldg(&((const float4*)(Wt + l * HID * HID))[tid + i * 512]);
        }
        __syncthreads();                      // Ws + Xs ready

        u64 acc[4][4];
#pragma unroll
        for (int pp = 0; pp < 4; pp++)
#pragma unroll
            for (int jp = 0; jp < 4; jp++) acc[pp][jp] = 0ull;

#pragma unroll 8
        for (int k = 0; k < HID; k++) {
            float4 a4 = *(const float4*)&Xs[k * XSTRIDE + pbase];
            ulonglong2 b0 = *(const ulonglong2*)&Ws[k * XSTRIDE + j0];
            ulonglong2 b1 = *(const ulonglong2*)&Ws[k * XSTRIDE + 64 + j0];
            u64 aa0 = pack2(a4.x, a4.x);
            u64 aa1 = pack2(a4.y, a4.y);
            u64 aa2 = pack2(a4.z, a4.z);
            u64 aa3 = pack2(a4.w, a4.w);
            ffma2(acc[0][0], aa0, b0.x); ffma2(acc[0][1], aa0, b0.y);
            ffma2(acc[0][2], aa0, b1.x); ffma2(acc[0][3], aa0, b1.y);
            ffma2(acc[1][0], aa1, b0.x); ffma2(acc[1][1], aa1, b0.y);
            ffma2(acc[1][2], aa1, b1.x); ffma2(acc[1][3], aa1, b1.y);
            ffma2(acc[2][0], aa2, b0.x); ffma2(acc[2][1], aa2, b0.y);
            ffma2(acc[2][2], aa2, b1.x); ffma2(acc[2][3], aa2, b1.y);
            ffma2(acc[3][0], aa3, b0.x); ffma2(acc[3][1], aa3, b0.y);
            ffma2(acc[3][2], aa3, b1.x); ffma2(acc[3][3], aa3, b1.y);
        }
        __syncthreads();                      // all Xs/Ws reads done

        // epilogue: rowdy + gate, write back transposed
        const float* bvec = bt + (l - 1) * HID;
        float val[4][8];
#pragma unroll
        for (int jp = 0; jp < 4; jp++) {
            // pair (jlo, jhi): jp 0->(j0,j0+1) 1->(j0+2,j0+3) 2->(64+j0,64+j0+1) 3->(64+j0+2,64+j0+3)
            int jlo = (jp < 2) ? (j0 + jp * 2) : (64 + j0 + (jp - 2) * 2);
            int jhi = jlo + 1;
            float btl = __ldg(&bvec[jlo]), bth = __ldg(&bvec[jhi]);
            float avl = __ldg(&at[l * HID + jlo]), avh = __ldg(&at[l * HID + jhi]);
            float wvl = __ldg(&wt[l * HID + jlo]), wvh = __ldg(&wt[l * HID + jhi]);
#pragma unroll
            for (int pp = 0; pp < 4; pp++) {
                float flo, fhi;
                unpack2(acc[pp][jp], flo, fhi);
                const float* grow = &g_gate[(l * NB + bidx[pp]) * HID];
                int jjlo = (jp < 2) ? (jp * 2) : (4 + (jp - 2) * 2);
                val[pp][jjlo]     = rowdy_f(flo + btl, avl, wvl) * __ldg(&grow[jlo]);
                val[pp][jjlo + 1] = rowdy_f(fhi + bth, avh, wvh) * __ldg(&grow[jhi]);
            }
        }
#pragma unroll
        for (int jj = 0; jj < 8; jj++) {
            float4 v = make_float4(val[0][jj], val[1][jj], val[2][jj], val[3][jj]);
            *(float4*)&Xs[jcol[jj] * XSTRIDE + pbase] = v;
        }
        __syncthreads();                      // Xs ready for next layer / final
    }

    // ---- folded final: out[p][o] = c[b][o] + sum_g Xs[g][p] * M[b][g][o] ----
    // 512 threads: 4 groups of 128, each group sums a quarter of g.
    {
        float* part = Ws;                     // reuse weight buffer: [5][4][128]
        const int p  = tid & 127;
        const int q  = tid >> 7;              // 0..3
        const int gp = p0 + p;
        const int b  = gp / NPTS;
        float o0 = 0.f, o1 = 0.f, o2 = 0.f, o3 = 0.f, o4 = 0.f;
        const float4* Mb = (const float4*)&g_M[b * HID * 8];
#pragma unroll 8
        for (int g = q * 32; g < q * 32 + 32; g++) {
            float v   = Xs[g * XSTRIDE + p];
            float4 m0 = __ldg(&Mb[g * 2 + 0]);
            float4 m1 = __ldg(&Mb[g * 2 + 1]);
            o0 += v * m0.x; o1 += v * m0.y; o2 += v * m0.z; o3 += v * m0.w;
            o4 += v * m1.x;
        }
        part[(0 * 4 + q) * 128 + p] = o0;
        part[(1 * 4 + q) * 128 + p] = o1;
        part[(2 * 4 + q) * 128 + p] = o2;
        part[(3 * 4 + q) * 128 + p] = o3;
        part[(4 * 4 + q) * 128 + p] = o4;
        __syncthreads();
        if (tid < 128) {
            const int pp2 = tid;
            const int gp2 = p0 + pp2;
            const int b2  = gp2 / NPTS;
            float* op = out + (size_t)gp2 * OUTD;
#pragma unroll
            for (int o = 0; o < OUTD; o++) {
                float s = g_c[b2 * 8 + o];
                s += part[(o * 4 + 0) * 128 + pp2];
                s += part[(o * 4 + 1) * 128 + pp2];
                s += part[(o * 4 + 2) * 128 + pp2];
                s += part[(o * 4 + 3) * 128 + pp2];
                op[o] = s;
            }
        }
    }
}

// ---------------------------------------------------------------------------
extern "C" void kernel_launch(void* const* d_in, const int* in_sizes, int n_in,
                              void* d_out, int out_size)
{
    const float* coords = (const float*)d_in[0];
    const float* sdf    = (const float*)d_in[1];
    const float* params = (const float*)d_in[2];
    const float* Wb0    = (const float*)d_in[3];
    const float* bb0    = (const float*)d_in[4];
    const float* Wb     = (const float*)d_in[5];
    const float* bb     = (const float*)d_in[6];
    const float* Wbf    = (const float*)d_in[7];
    const float* bbf    = (const float*)d_in[8];
    const float* ab     = (const float*)d_in[9];
    const float* wb     = (const float*)d_in[10];
    const float* Wt0    = (const float*)d_in[11];
    const float* bt0    = (const float*)d_in[12];
    const float* Wt     = (const float*)d_in[13];
    const float* bt     = (const float*)d_in[14];
    const float* Wtf    = (const float*)d_in[15];
    const float* btf    = (const float*)d_in[16];
    const float* at     = (const float*)d_in[17];
    const float* wt     = (const float*)d_in[18];
    float* out = (float*)d_out;

    static int smem_set = 0;
    const int smem_bytes = 2 * HID * XSTRIDE * sizeof(float);   // 135168
    if (!smem_set) {
        cudaFuncSetAttribute(trunk_kernel,
                             cudaFuncAttributeMaxDynamicSharedMemorySize,
                             smem_bytes);
        smem_set = 1;
    }

    branch_kernel<<<NB, HID>>>(params, Wb0, bb0, Wb, bb, Wbf, bbf, ab, wb,
                               Wtf, btf);
    trunk_kernel<<<LTOT / 128, 512, smem_bytes>>>(coords, sdf, Wt0, bt0,
                                                  Wt, bt, at, wt, out);
}

// round 3
// speedup vs baseline: 1.2214x; 1.0213x over previous
#include <cuda_runtime.h>

#define HID   128
#define NB    16
#define NPTS  10000
#define OUTD  5
#define LTOT  (NB * NPTS)      // 160000 points
#define BP    256              // points per block
#define WSTRIDE 132            // weight smem stride (floats)

// Scratch (device globals — no allocation allowed)
__device__ float g_gate[4 * NB * HID];   // gates per layer/batch/feature
__device__ float g_M[NB * HID * 8];      // folded gate3*(Wtf@bc^T), padded to 8/[b,g]
__device__ float g_c[NB * 8];            // folded btf·bc

typedef unsigned long long u64;

__device__ __forceinline__ u64 pack2(float lo, float hi) {
    u64 r; asm("mov.b64 %0, {%1, %2};" : "=l"(r) : "f"(lo), "f"(hi)); return r;
}
__device__ __forceinline__ void unpack2(u64 v, float& lo, float& hi) {
    asm("mov.b64 {%0, %1}, %2;" : "=f"(lo), "=f"(hi) : "l"(v));
}
__device__ __forceinline__ void ffma2(u64& d, u64 a, u64 b) {
    asm("fma.rn.f32x2 %0, %1, %2, %0;" : "+l"(d) : "l"(a), "l"(b));
}
__device__ __forceinline__ float rowdy_f(float t, float a, float w) {
    float th; asm("tanh.approx.f32 %0, %1;" : "=f"(th) : "f"(t));
    return th + a * __sinf(w * t);
}
// swizzled float offset into Xs[k][p] (256 floats per row, XOR on bits[2:4] of p)
__device__ __forceinline__ int xswz(int k, int p) {
    return k * BP + (p ^ (((k >> 2) & 7) << 2));
}
__device__ __forceinline__ void cp_async16(void* smem_dst, const void* gmem_src) {
    unsigned sm = (unsigned)__cvta_generic_to_shared(smem_dst);
    asm volatile("cp.async.cg.shared.global [%0], [%1], 16;" :: "r"(sm), "l"(gmem_src));
}

// ---------------------------------------------------------------------------
// Kernel 1: branch MLP, gates, folded final matrices. grid=16, block=128.
// ---------------------------------------------------------------------------
__global__ void branch_kernel(
    const float* __restrict__ params, const float* __restrict__ Wb0,
    const float* __restrict__ bb0,    const float* __restrict__ Wb,
    const float* __restrict__ bb,     const float* __restrict__ Wbf,
    const float* __restrict__ bbf,    const float* __restrict__ ab,
    const float* __restrict__ wb,     const float* __restrict__ Wtf,
    const float* __restrict__ btf)
{
    const int b = blockIdx.x;
    const int j = threadIdx.x;

    __shared__ float sh_h[HID];
    __shared__ float sh_bc[OUTD][HID];
    __shared__ float sh_p[8];

    if (j < 6) sh_p[j] = params[b * 6 + j];
    __syncthreads();

    float t = bb0[j];
#pragma unroll
    for (int k = 0; k < 6; k++) t += sh_p[k] * Wb0[k * HID + j];
    float h    = rowdy_f(t, ab[j], wb[j]);
    float gate = h;
    sh_h[j] = h;
    g_gate[(0 * NB + b) * HID + j] = gate;
    __syncthreads();

    for (int i = 0; i < 3; i++) {
        const float* W = Wb + i * HID * HID;
        float t2 = bb[i * HID + j];
#pragma unroll 8
        for (int k = 0; k < HID; k++) t2 += sh_h[k] * W[k * HID + j];
        __syncthreads();
        h = rowdy_f(t2, ab[(i + 1) * HID + j], wb[(i + 1) * HID + j]);
        sh_h[j] = h;
        gate += h;
        g_gate[((i + 1) * NB + b) * HID + j] = gate;
        __syncthreads();
    }
    // gate now = gate3[b][j]

#pragma unroll
    for (int o = 0; o < OUTD; o++) {
        float s = bbf[o * HID + j];
#pragma unroll 8
        for (int k = 0; k < HID; k++)
            s += sh_h[k] * Wbf[k * (HID * OUTD) + o * HID + j];
        sh_bc[o][j] = s;
    }
    __syncthreads();

    // M'[b][g][o] = gate3[g] * sum_h Wtf[g][h]*bc[o][h];  c[b][o] = btf·bc[o]
    {
        float accm[OUTD] = {0.f, 0.f, 0.f, 0.f, 0.f};
#pragma unroll 4
        for (int hh = 0; hh < HID; hh++) {
            float w = __ldg(&Wtf[j * HID + hh]);
#pragma unroll
            for (int o = 0; o < OUTD; o++) accm[o] += w * sh_bc[o][hh];
        }
#pragma unroll
        for (int o = 0; o < OUTD; o++) g_M[(b * HID + j) * 8 + o] = accm[o] * gate;
        for (int o = OUTD; o < 8; o++) g_M[(b * HID + j) * 8 + o] = 0.f;
    }
    if (j < OUTD) {
        float c = 0.f;
#pragma unroll 8
        for (int hh = 0; hh < HID; hh++) c += btf[hh] * sh_bc[j][hh];
        g_c[b * 8 + j] = c;
    }
    if (j >= OUTD && j < 8) g_c[b * 8 + j] = 0.f;
}

// ---------------------------------------------------------------------------
// Kernel 2: fused trunk. Block = 256 points x 128 features, 512 threads,
// 8x8 register tile, packed f32x2 FMAs, cp.async weight staging, swizzled
// activation buffer.
// ---------------------------------------------------------------------------
extern "C" __global__ void __launch_bounds__(512, 1)
trunk_kernel(const float* __restrict__ coords, const float* __restrict__ sdf,
             const float* __restrict__ Wt0,    const float* __restrict__ bt0,
             const float* __restrict__ Wt,     const float* __restrict__ bt,
             const float* __restrict__ at,     const float* __restrict__ wt,
             float* __restrict__ out)
{
    extern __shared__ float smem[];
    float* Xs = smem;                       // [128][256] swizzled activations
    float* Ws = smem + HID * BP;            // [128][WSTRIDE] weights

    const int tid    = threadIdx.x;
    const int tx     = tid & 15;
    const int ty     = tid >> 4;            // 0..31
    const int p0     = blockIdx.x * BP;
    const int j0     = tx * 4;
    const int pbase  = ty * 8;
    const int bstart = p0 / NPTS;
    const int bound  = (bstart + 1) * NPTS - p0;   // points < bound -> bstart

    // kick off layer-1 weight staging immediately
#pragma unroll
    for (int i = 0; i < 8; i++) {
        int idx = tid + i * 512;
        int r = idx >> 5, c = (idx & 31) * 4;
        cp_async16(&Ws[r * WSTRIDE + c], &((const float4*)Wt)[idx]);
    }
    asm volatile("cp.async.commit_group;");

    int jcol[8];
#pragma unroll
    for (int i = 0; i < 4; i++) { jcol[i] = j0 + i; jcol[i + 4] = 64 + j0 + i; }

    // ---- layer 0: (coords,sdf) 4 -> 128 ----
    {
        float w0[8][4];
#pragma unroll
        for (int jj = 0; jj < 8; jj++)
#pragma unroll
            for (int k = 0; k < 4; k++)
                w0[jj][k] = __ldg(&Wt0[k * HID + jcol[jj]]);

        float btv[8], av[8], wv[8];
#pragma unroll
        for (int jj = 0; jj < 8; jj++) {
            int j = jcol[jj];
            btv[jj] = __ldg(&bt0[j]);
            av[jj]  = __ldg(&at[j]);
            wv[jj]  = __ldg(&wt[j]);
        }
#pragma unroll
        for (int pp = 0; pp < 8; pp++) {
            int gp = p0 + pbase + pp;
            float c0 = coords[gp * 3 + 0];
            float c1 = coords[gp * 3 + 1];
            float c2 = coords[gp * 3 + 2];
            float c3 = sdf[gp];
            int b = (pbase + pp < bound) ? bstart : bstart + 1;
            const float* grow = &g_gate[(0 * NB + b) * HID];
#pragma unroll
            for (int jj = 0; jj < 8; jj++) {
                float s = btv[jj];
                s += c0 * w0[jj][0]; s += c1 * w0[jj][1];
                s += c2 * w0[jj][2]; s += c3 * w0[jj][3];
                Xs[xswz(jcol[jj], pbase + pp)] =
                    rowdy_f(s, av[jj], wv[jj]) * __ldg(&grow[jcol[jj]]);
            }
        }
    }
    asm volatile("cp.async.wait_group 0;");
    __syncthreads();

    // ---- layers 1..3 ----
    for (int l = 1; l < 4; l++) {
        u64 acc[8][4];
#pragma unroll
        for (int pp = 0; pp < 8; pp++)
#pragma unroll
            for (int jp = 0; jp < 4; jp++) acc[pp][jp] = 0ull;

#pragma unroll 8
        for (int k = 0; k < HID; k++) {
            float4 a0 = *(const float4*)&Xs[xswz(k, pbase)];
            float4 a1 = *(const float4*)&Xs[xswz(k, pbase + 4)];
            ulonglong2 b0 = *(const ulonglong2*)&Ws[k * WSTRIDE + j0];
            ulonglong2 b1 = *(const ulonglong2*)&Ws[k * WSTRIDE + 64 + j0];
            u64 s0 = pack2(a0.x, a0.x), s1 = pack2(a0.y, a0.y);
            u64 s2 = pack2(a0.z, a0.z), s3 = pack2(a0.w, a0.w);
            u64 s4 = pack2(a1.x, a1.x), s5 = pack2(a1.y, a1.y);
            u64 s6 = pack2(a1.z, a1.z), s7 = pack2(a1.w, a1.w);
            ffma2(acc[0][0], s0, b0.x); ffma2(acc[0][1], s0, b0.y);
            ffma2(acc[0][2], s0, b1.x); ffma2(acc[0][3], s0, b1.y);
            ffma2(acc[1][0], s1, b0.x); ffma2(acc[1][1], s1, b0.y);
            ffma2(acc[1][2], s1, b1.x); ffma2(acc[1][3], s1, b1.y);
            ffma2(acc[2][0], s2, b0.x); ffma2(acc[2][1], s2, b0.y);
            ffma2(acc[2][2], s2, b1.x); ffma2(acc[2][3], s2, b1.y);
            ffma2(acc[3][0], s3, b0.x); ffma2(acc[3][1], s3, b0.y);
            ffma2(acc[3][2], s3, b1.x); ffma2(acc[3][3], s3, b1.y);
            ffma2(acc[4][0], s4, b0.x); ffma2(acc[4][1], s4, b0.y);
            ffma2(acc[4][2], s4, b1.x); ffma2(acc[4][3], s4, b1.y);
            ffma2(acc[5][0], s5, b0.x); ffma2(acc[5][1], s5, b0.y);
            ffma2(acc[5][2], s5, b1.x); ffma2(acc[5][3], s5, b1.y);
            ffma2(acc[6][0], s6, b0.x); ffma2(acc[6][1], s6, b0.y);
            ffma2(acc[6][2], s6, b1.x); ffma2(acc[6][3], s6, b1.y);
            ffma2(acc[7][0], s7, b0.x); ffma2(acc[7][1], s7, b0.y);
            ffma2(acc[7][2], s7, b1.x); ffma2(acc[7][3], s7, b1.y);
        }
        __syncthreads();                      // all Xs/Ws reads done

        // stage next layer's weights while epilogue runs
        if (l < 3) {
#pragma unroll
            for (int i = 0; i < 8; i++) {
                int idx = tid + i * 512;
                int r = idx >> 5, c = (idx & 31) * 4;
                cp_async16(&Ws[r * WSTRIDE + c],
                           &((const float4*)(Wt + l * HID * HID))[idx]);
            }
            asm volatile("cp.async.commit_group;");
        }

        // epilogue: rowdy (+ gate for l<3; gate3 folded into M'), transposed store
        const float* bvec = bt + (l - 1) * HID;
        float val[8][8];
#pragma unroll
        for (int jp = 0; jp < 4; jp++) {
            int jlo = (jp < 2) ? (j0 + jp * 2) : (64 + j0 + (jp - 2) * 2);
            int jhi = jlo + 1;
            int jjlo = (jp < 2) ? (jp * 2) : (4 + (jp - 2) * 2);
            float btl = __ldg(&bvec[jlo]), bth = __ldg(&bvec[jhi]);
            float avl = __ldg(&at[l * HID + jlo]), avh = __ldg(&at[l * HID + jhi]);
            float wvl = __ldg(&wt[l * HID + jlo]), wvh = __ldg(&wt[l * HID + jhi]);
#pragma unroll
            for (int pp = 0; pp < 8; pp++) {
                float flo, fhi;
                unpack2(acc[pp][jp], flo, fhi);
                float r0 = rowdy_f(flo + btl, avl, wvl);
                float r1 = rowdy_f(fhi + bth, avh, wvh);
                if (l < 3) {
                    int b = (pbase + pp < bound) ? bstart : bstart + 1;
                    const float* grow = &g_gate[(l * NB + b) * HID];
                    r0 *= __ldg(&grow[jlo]);
                    r1 *= __ldg(&grow[jhi]);
                }
                val[pp][jjlo] = r0; val[pp][jjlo + 1] = r1;
            }
        }
#pragma unroll
        for (int jj = 0; jj < 8; jj++) {
            float4 v0 = make_float4(val[0][jj], val[1][jj], val[2][jj], val[3][jj]);
            float4 v1 = make_float4(val[4][jj], val[5][jj], val[6][jj], val[7][jj]);
            *(float4*)&Xs[xswz(jcol[jj], pbase)]     = v0;
            *(float4*)&Xs[xswz(jcol[jj], pbase + 4)] = v1;
        }
        if (l < 3) asm volatile("cp.async.wait_group 0;");
        __syncthreads();
    }

    // ---- folded final: out[p][o] = c[b][o] + sum_g Xs[g][p] * M'[b][g][o] ----
    {
        float* part = Ws;                     // reuse: [5][2][256]
        const int p = tid & 255;
        const int q = tid >> 8;               // 0..1, each sums 64 g's
        const int b = (p < bound) ? bstart : bstart + 1;
        float o0 = 0.f, o1 = 0.f, o2 = 0.f, o3 = 0.f, o4 = 0.f;
        const float4* Mb = (const float4*)&g_M[b * HID * 8];
#pragma unroll 8
        for (int g = q * 64; g < q * 64 + 64; g++) {
            float v   = Xs[xswz(g, p)];
            float4 m0 = __ldg(&Mb[g * 2 + 0]);
            float4 m1 = __ldg(&Mb[g * 2 + 1]);
            o0 += v * m0.x; o1 += v * m0.y; o2 += v * m0.z; o3 += v * m0.w;
            o4 += v * m1.x;
        }
        part[(0 * 2 + q) * 256 + p] = o0;
        part[(1 * 2 + q) * 256 + p] = o1;
        part[(2 * 2 + q) * 256 + p] = o2;
        part[(3 * 2 + q) * 256 + p] = o3;
        part[(4 * 2 + q) * 256 + p] = o4;
        __syncthreads();
        if (tid < BP) {
            const int pp2 = tid;
            const int gp2 = p0 + pp2;
            const int b2  = (pp2 < bound) ? bstart : bstart + 1;
            float* op = out + (size_t)gp2 * OUTD;
#pragma unroll
            for (int o = 0; o < OUTD; o++)
                op[o] = g_c[b2 * 8 + o]
                      + part[(o * 2 + 0) * 256 + pp2]
                      + part[(o * 2 + 1) * 256 + pp2];
        }
    }
}

// ---------------------------------------------------------------------------
extern "C" void kernel_launch(void* const* d_in, const int* in_sizes, int n_in,
                              void* d_out, int out_size)
{
    const float* coords = (const float*)d_in[0];
    const float* sdf    = (const float*)d_in[1];
    const float* params = (const float*)d_in[2];
    const float* Wb0    = (const float*)d_in[3];
    const float* bb0    = (const float*)d_in[4];
    const float* Wb     = (const float*)d_in[5];
    const float* bb     = (const float*)d_in[6];
    const float* Wbf    = (const float*)d_in[7];
    const float* bbf    = (const float*)d_in[8];
    const float* ab     = (const float*)d_in[9];
    const float* wb     = (const float*)d_in[10];
    const float* Wt0    = (const float*)d_in[11];
    const float* bt0    = (const float*)d_in[12];
    const float* Wt     = (const float*)d_in[13];
    const float* bt     = (const float*)d_in[14];
    const float* Wtf    = (const float*)d_in[15];
    const float* btf    = (const float*)d_in[16];
    const float* at     = (const float*)d_in[17];
    const float* wt     = (const float*)d_in[18];
    float* out = (float*)d_out;

    static int smem_set = 0;
    const int smem_bytes = (HID * BP + HID * WSTRIDE) * sizeof(float);  // 198656
    if (!smem_set) {
        cudaFuncSetAttribute(trunk_kernel,
                             cudaFuncAttributeMaxDynamicSharedMemorySize,
                             smem_bytes);
        smem_set = 1;
    }

    branch_kernel<<<NB, HID>>>(params, Wb0, bb0, Wb, bb, Wbf, bbf, ab, wb,
                               Wtf, btf);
    trunk_kernel<<<LTOT / BP, 512, smem_bytes>>>(coords, sdf, Wt0, bt0,
                                                 Wt, bt, at, wt, out);
}